// round 1
// baseline (speedup 1.0000x reference)
#include <cuda_runtime.h>
#include <cuda_bf16.h>
#include <math.h>

// Problem constants (fixed by dataset)
#define N_NODES 100000   // both N_C and N_P
#define D_IN    64
#define D_H     32
#define E_EDGES 1600000

// ---------------- scratch (device globals; no allocation allowed) ----------
__device__ float g_aggp[N_NODES * D_H];   // layer1 aggregation into products
__device__ float g_aggc[N_NODES * D_H];   // layer1 aggregation into customers
__device__ float g_ycp [N_NODES * D_H];   // x_customer @ W1l_r1
__device__ float g_ypc [N_NODES * D_H];   // x_product  @ W1l_r2
__device__ float g_cntp[N_NODES];
__device__ float g_cntc[N_NODES];
__device__ float g_gc  [N_NODES];         // per-customer scalar dot(relu(h_c), w2l_eff)
__device__ float g_gp  [N_NODES];         // per-product  scalar dot(relu(h_p), w2r_eff)
__device__ float g_aggs[N_NODES];         // layer2 scalar aggregation into products
__device__ float g_w2l_eff[D_H];
__device__ float g_w2r_eff[D_H];
__device__ float g_bias_eff[1];

// ---------------- kernels ---------------------------------------------------

__global__ void k_zero(float* __restrict__ p, int n) {
    int i = blockIdx.x * blockDim.x + threadIdx.x;
    if (i < n) p[i] = 0.0f;
}

// Effective layer2+head weights: w_eff[i] = sum_j W2[i][j] * Wlin[j]
__global__ void k_eff(const float* __restrict__ W2l, const float* __restrict__ W2r,
                      const float* __restrict__ b2, const float* __restrict__ Wlin,
                      const float* __restrict__ blin) {
    int i = threadIdx.x;  // 0..31
    float wl = 0.f, wr = 0.f;
    #pragma unroll
    for (int j = 0; j < D_H; ++j) {
        float wj = Wlin[j];
        wl += W2l[i * D_H + j] * wj;
        wr += W2r[i * D_H + j] * wj;
    }
    g_w2l_eff[i] = wl;
    g_w2r_eff[i] = wr;
    float bv = b2[i] * Wlin[i];
    #pragma unroll
    for (int o = 16; o; o >>= 1) bv += __shfl_xor_sync(0xffffffffu, bv, o);
    if (i == 0) g_bias_eff[0] = bv + blin[0];
}

// y[n,32] = x[n,64] @ W[64,32]. 8 nodes per 256-thread block.
__global__ void k_proj(const float* __restrict__ x, const float* __restrict__ W,
                       float* __restrict__ y, int n) {
    __shared__ float sW[D_IN * D_H];      // 8KB
    __shared__ float sx[8][D_IN];         // 2KB
    int tid = threadIdx.x;
    #pragma unroll
    for (int i = tid; i < D_IN * D_H; i += 256) sW[i] = W[i];
    int nodeBase = blockIdx.x * 8;
    for (int i = tid; i < 8 * D_IN; i += 256) {
        int node = nodeBase + (i >> 6);
        sx[i >> 6][i & 63] = (node < n) ? x[(size_t)node * D_IN + (i & 63)] : 0.f;
    }
    __syncthreads();
    int local = tid >> 5, j = tid & 31;
    int node = nodeBase + local;
    if (node >= n) return;
    float acc = 0.f;
    #pragma unroll
    for (int k = 0; k < D_IN; ++k) acc += sx[local][k] * sW[k * D_H + j];
    y[(size_t)node * D_H + j] = acc;
}

// Per-edge scatter of 32-float rows + degree count. 8 threads/edge (float4 each).
__global__ void k_scatter32(const int* __restrict__ edge, const float* __restrict__ feat,
                            float* __restrict__ agg, float* __restrict__ cnt, int E) {
    long long t = (long long)blockIdx.x * blockDim.x + threadIdx.x;
    int e    = (int)(t >> 3);
    int lane = (int)(t & 7);
    if (e >= E) return;
    int s = __ldg(&edge[e]);
    int d = __ldg(&edge[E + e]);
    float4 v = *reinterpret_cast<const float4*>(feat + (size_t)s * D_H + lane * 4);
    atomicAdd(reinterpret_cast<float4*>(agg + (size_t)d * D_H + lane * 4), v);
    if (lane == 0) atomicAdd(cnt + d, 1.0f);
}

// Per-node: h = relu(agg/max(cnt,1) + b + x@Wr); g = dot(h, weff). Warp per node.
__global__ void k_node(const float* __restrict__ x, const float* __restrict__ Wr,
                       const float* __restrict__ b, const float* __restrict__ agg,
                       const float* __restrict__ cnt, const float* __restrict__ weff,
                       float* __restrict__ g, int n) {
    __shared__ float sW[D_IN * D_H];
    #pragma unroll
    for (int i = threadIdx.x; i < D_IN * D_H; i += 256) sW[i] = Wr[i];
    __syncthreads();
    int warp = threadIdx.x >> 5, j = threadIdx.x & 31;
    int node = blockIdx.x * 8 + warp;
    if (node >= n) return;
    float xa = x[(size_t)node * D_IN + j];
    float xb = x[(size_t)node * D_IN + 32 + j];
    float acc = b[j];
    #pragma unroll
    for (int k = 0; k < 32; ++k)
        acc += __shfl_sync(0xffffffffu, xa, k) * sW[k * D_H + j];
    #pragma unroll
    for (int k = 0; k < 32; ++k)
        acc += __shfl_sync(0xffffffffu, xb, k) * sW[(k + 32) * D_H + j];
    float c = cnt[node];
    float h = acc + agg[(size_t)node * D_H + j] / fmaxf(c, 1.0f);
    h = fmaxf(h, 0.0f);
    float v = h * weff[j];
    #pragma unroll
    for (int o = 16; o; o >>= 1) v += __shfl_xor_sync(0xffffffffu, v, o);
    if (j == 0) g[node] = v;
}

// Layer-2 scalar scatter: aggs[dst] += g_c[src]
__global__ void k_scatter_scalar(const int* __restrict__ edge, const float* __restrict__ gsrc,
                                 float* __restrict__ aggs, int E) {
    int e = blockIdx.x * blockDim.x + threadIdx.x;
    if (e >= E) return;
    int s = __ldg(&edge[e]);
    int d = __ldg(&edge[E + e]);
    atomicAdd(aggs + d, gsrc[s]);
}

// out[p] = sigmoid(aggs/max(cnt,1) + g_p + bias_eff)
__global__ void k_final(float* __restrict__ out, int n) {
    int i = blockIdx.x * blockDim.x + threadIdx.x;
    if (i >= n) return;
    float logit = g_aggs[i] / fmaxf(g_cntp[i], 1.0f) + g_gp[i] + g_bias_eff[0];
    out[i] = 1.0f / (1.0f + expf(-logit));
}

// ---------------- launch ----------------------------------------------------

extern "C" void kernel_launch(void* const* d_in, const int* in_sizes, int n_in,
                              void* d_out, int out_size) {
    const float* x_customer = (const float*)d_in[0];
    const float* x_product  = (const float*)d_in[1];
    const int*   edge_c2p   = (const int*)d_in[2];
    const int*   edge_p2c   = (const int*)d_in[3];
    const float* W1l_r1 = (const float*)d_in[4];
    const float* b1_r1  = (const float*)d_in[5];
    const float* W1r_r1 = (const float*)d_in[6];
    const float* W1l_r2 = (const float*)d_in[7];
    const float* b1_r2  = (const float*)d_in[8];
    const float* W1r_r2 = (const float*)d_in[9];
    const float* W2l_r1 = (const float*)d_in[10];
    const float* b2_r1  = (const float*)d_in[11];
    const float* W2r_r1 = (const float*)d_in[12];
    // d_in[13..15] (W2l_r2, b2_r2, W2r_r2) are unused by the reference graph.
    const float* Wlin   = (const float*)d_in[16];
    const float* blin   = (const float*)d_in[17];
    float* out = (float*)d_out;

    const int N = N_NODES;
    const int E = in_sizes[2] / 2;

    float *p_aggp, *p_aggc, *p_ycp, *p_ypc, *p_cntp, *p_cntc, *p_gc, *p_gp, *p_aggs;
    float *p_w2l, *p_w2r;
    cudaGetSymbolAddress((void**)&p_aggp, g_aggp);
    cudaGetSymbolAddress((void**)&p_aggc, g_aggc);
    cudaGetSymbolAddress((void**)&p_ycp,  g_ycp);
    cudaGetSymbolAddress((void**)&p_ypc,  g_ypc);
    cudaGetSymbolAddress((void**)&p_cntp, g_cntp);
    cudaGetSymbolAddress((void**)&p_cntc, g_cntc);
    cudaGetSymbolAddress((void**)&p_gc,   g_gc);
    cudaGetSymbolAddress((void**)&p_gp,   g_gp);
    cudaGetSymbolAddress((void**)&p_aggs, g_aggs);
    cudaGetSymbolAddress((void**)&p_w2l,  g_w2l_eff);
    cudaGetSymbolAddress((void**)&p_w2r,  g_w2r_eff);

    const int TB = 256;
    // zero scratch accumulators
    k_zero<<<(N * D_H + TB - 1) / TB, TB>>>(p_aggp, N * D_H);
    k_zero<<<(N * D_H + TB - 1) / TB, TB>>>(p_aggc, N * D_H);
    k_zero<<<(N + TB - 1) / TB, TB>>>(p_cntp, N);
    k_zero<<<(N + TB - 1) / TB, TB>>>(p_cntc, N);
    k_zero<<<(N + TB - 1) / TB, TB>>>(p_aggs, N);

    // effective layer2 + head weights
    k_eff<<<1, 32>>>(W2l_r1, W2r_r1, b2_r1, Wlin, blin);

    // dense projections (pre-aggregation transform)
    int projBlocks = (N + 7) / 8;
    k_proj<<<projBlocks, TB>>>(x_customer, W1l_r1, p_ycp, N);
    k_proj<<<projBlocks, TB>>>(x_product,  W1l_r2, p_ypc, N);

    // layer1 edge scatters (32 floats + count per edge)
    long long scatThreads = (long long)E * 8;
    int scatBlocks = (int)((scatThreads + TB - 1) / TB);
    k_scatter32<<<scatBlocks, TB>>>(edge_c2p, p_ycp, p_aggp, p_cntp, E);
    k_scatter32<<<scatBlocks, TB>>>(edge_p2c, p_ypc, p_aggc, p_cntc, E);

    // per-node transforms + fold layer2/head into scalars
    k_node<<<projBlocks, TB>>>(x_product,  W1r_r1, b1_r1, p_aggp, p_cntp, p_w2r, p_gp, N);
    k_node<<<projBlocks, TB>>>(x_customer, W1r_r2, b1_r2, p_aggc, p_cntc, p_w2l, p_gc, N);

    // layer2 scalar scatter over c2p edges
    k_scatter_scalar<<<(E + TB - 1) / TB, TB>>>(edge_c2p, p_gc, p_aggs, E);

    // epilogue
    k_final<<<(N + TB - 1) / TB, TB>>>(out, N);
}